// round 9
// baseline (speedup 1.0000x reference)
#include <cuda_runtime.h>
#include <cuda_fp16.h>
#include <cstdint>
#include <cstddef>

// ---------------- problem dims (fixed) ----------------
#define N_B    64
#define T_DIM  64
#define TM1    63
#define DX     16
#define DU     8
#define H_DIM  256
#define L_DIM  128
#define K_NETS 64
#define MX     (N_B * T_DIM)   // 4096
#define MU     (N_B * TM1)     // 4032
#define KP1    32              // padded K for layer 1
#define MT_PER_BLK 8           // m-tiles per persistent block

// ---------------- scratch (device globals) ----------------
__device__ __half g_xnhi[MX * KP1];
__device__ __half g_xnlo[MX * KP1];
__device__ __half g_unhi[MU * KP1];
__device__ __half g_unlo[MU * KP1];
__device__ float g_b1ex[K_NETS * H_DIM];
__device__ float g_b1eu[K_NETS * H_DIM];
__device__ __half g_w1xh[K_NETS * H_DIM * KP1];
__device__ __half g_w1xl[K_NETS * H_DIM * KP1];
__device__ __half g_w1uh[K_NETS * H_DIM * KP1];
__device__ __half g_w1ul[K_NETS * H_DIM * KP1];
__device__ __half g_h1[(size_t)K_NETS * MX * H_DIM];
__device__ __half g_h2[(size_t)K_NETS * MX * H_DIM];
__device__ __half g_w2xt_hi[(size_t)K_NETS * H_DIM * H_DIM];
__device__ __half g_w2xt_lo[(size_t)K_NETS * H_DIM * H_DIM];
__device__ __half g_w3xt_hi[(size_t)K_NETS * L_DIM * H_DIM];
__device__ __half g_w3xt_lo[(size_t)K_NETS * L_DIM * H_DIM];
__device__ __half g_w2ut_hi[(size_t)K_NETS * H_DIM * H_DIM];
__device__ __half g_w2ut_lo[(size_t)K_NETS * H_DIM * H_DIM];
__device__ __half g_w3ut_hi[(size_t)K_NETS * L_DIM * H_DIM];
__device__ __half g_w3ut_lo[(size_t)K_NETS * L_DIM * H_DIM];
__device__ float g_phi[(size_t)MX * K_NETS * L_DIM];      // [m][net][L]
__device__ float g_psi[(size_t)MU * K_NETS * L_DIM];      // [bt][net][L]
__device__ float g_psi0[K_NETS * L_DIM];
__device__ float g_phisum[MX * L_DIM];
__device__ float g_predsum2[2 * N_B * TM1 * L_DIM];

// ---------------- BN + fp16 hi/lo split ----------------
__global__ void bn_split_kernel(const float* __restrict__ x,
                                __half* __restrict__ Ahi,
                                __half* __restrict__ Alo,
                                int M, int D) {
    int d = blockIdx.x;
    int tid = threadIdx.x;
    if (d >= D) {
        for (int m = tid; m < M; m += 256) {
            Ahi[(size_t)m * KP1 + d] = __float2half(0.f);
            Alo[(size_t)m * KP1 + d] = __float2half(0.f);
        }
        return;
    }
    __shared__ float r1[256], r2[256];
    float s = 0.f, s2 = 0.f;
    for (int m = tid; m < M; m += 256) {
        float v = x[(size_t)m * D + d];
        s += v; s2 += v * v;
    }
    r1[tid] = s; r2[tid] = s2;
    __syncthreads();
    for (int o = 128; o > 0; o >>= 1) {
        if (tid < o) { r1[tid] += r1[tid + o]; r2[tid] += r2[tid + o]; }
        __syncthreads();
    }
    float mu = r1[0] / M;
    float var = r2[0] / M - mu * mu;
    float rstd = rsqrtf(var + 1e-5f);
    for (int m = tid; m < M; m += 256) {
        float v = (x[(size_t)m * D + d] - mu) * rstd;
        __half h = __float2half(v);
        Ahi[(size_t)m * KP1 + d] = h;
        Alo[(size_t)m * KP1 + d] = __float2half(v - __half2float(h));
    }
}

// ---------------- fold BN affine into layer-1, transpose, split ----------------
__global__ void prep_w1_split_kernel(const float* __restrict__ g, const float* __restrict__ be,
                                     const float* __restrict__ W1, const float* __restrict__ b1,
                                     __half* __restrict__ Thi,
                                     __half* __restrict__ Tlo,
                                     float* __restrict__ beff, int D) {
    int k = blockIdx.x;
    int h = threadIdx.x;
    float bacc = b1[k * H_DIM + h];
    for (int d = 0; d < KP1; d++) {
        float v = 0.f;
        if (d < D) {
            float w = W1[((size_t)k * D + d) * H_DIM + h];
            v = g[k * D + d] * w;
            bacc += be[k * D + d] * w;
        }
        __half hi = __float2half(v);
        size_t o = ((size_t)k * H_DIM + h) * KP1 + d;
        Thi[o] = hi;
        Tlo[o] = __float2half(v - __half2float(hi));
    }
    beff[k * H_DIM + h] = bacc;
}

// ---------------- merged W2+W3 transpose + split ----------------
__global__ void transpose_split2_kernel(const float* __restrict__ W2,
                                        __half* __restrict__ T2h,
                                        __half* __restrict__ T2l,
                                        const float* __restrict__ W3,
                                        __half* __restrict__ T3h,
                                        __half* __restrict__ T3l) {
    __shared__ float tile[32][33];
    int k = blockIdx.y;
    int idx = blockIdx.x;
    const float* W;
    __half *Th, *Tl;
    int N, kk0, n0;
    if (idx < 64) {
        W = W2 + (size_t)k * H_DIM * H_DIM;
        Th = T2h + (size_t)k * H_DIM * H_DIM;
        Tl = T2l + (size_t)k * H_DIM * H_DIM;
        N = H_DIM; kk0 = (idx >> 3) * 32; n0 = (idx & 7) * 32;
    } else {
        idx -= 64;
        W = W3 + (size_t)k * H_DIM * L_DIM;
        Th = T3h + (size_t)k * L_DIM * H_DIM;
        Tl = T3l + (size_t)k * L_DIM * H_DIM;
        N = L_DIM; kk0 = (idx >> 2) * 32; n0 = (idx & 3) * 32;
    }
    for (int r = threadIdx.y; r < 32; r += 8)
        tile[r][threadIdx.x] = W[(size_t)(kk0 + r) * N + n0 + threadIdx.x];
    __syncthreads();
    for (int r = threadIdx.y; r < 32; r += 8) {
        int n = n0 + r, kk = kk0 + threadIdx.x;
        float v = tile[threadIdx.x][r];
        __half h = __float2half(v);
        size_t o = (size_t)n * H_DIM + kk;
        Th[o] = h;
        Tl[o] = __float2half(v - __half2float(h));
    }
}

// ================= B-resident persistent HMMA batched GEMM (fp16) =================
// ASPLIT=true : C = (Ahi+Alo)@(Bh+Bl)^T (3 MMA terms)     — layer 1, KdPad=32
// ASPLIT=false: C = A@(Bh+Bl)^T        (2 MMA terms)      — layers 2/3, KdPad=256
// B (hi+lo, full K) resident in smem; block loops over MT_PER_BLK m-tiles with
// a continuous cross-tile cp.async A pipeline.
#define A_STRIDE 40
#define A_PLANE  (128 * A_STRIDE)             // halves

__device__ __forceinline__ void cp16(void* dst, const void* src, bool pred) {
    uint32_t d = (uint32_t)__cvta_generic_to_shared(dst);
    int n = pred ? 16 : 0;
    asm volatile("cp.async.cg.shared.global [%0], [%1], 16, %2;" :: "r"(d), "l"(src), "r"(n));
}
#define CP_COMMIT() asm volatile("cp.async.commit_group;")
#define CP_WAIT(N)  asm volatile("cp.async.wait_group %0;" :: "n"(N))

__device__ __forceinline__ void ldsm_x4(uint32_t* r, const void* p) {
    uint32_t a = (uint32_t)__cvta_generic_to_shared(p);
    asm volatile("ldmatrix.sync.aligned.m8n8.x4.shared.b16 {%0,%1,%2,%3}, [%4];"
                 : "=r"(r[0]), "=r"(r[1]), "=r"(r[2]), "=r"(r[3]) : "r"(a));
}
#define MMA16816(d, a, b0, b1) \
    asm volatile("mma.sync.aligned.m16n8k16.row.col.f32.f16.f16.f32 " \
                 "{%0,%1,%2,%3},{%4,%5,%6,%7},{%8,%9},{%0,%1,%2,%3};" \
                 : "+f"((d)[0]), "+f"((d)[1]), "+f"((d)[2]), "+f"((d)[3]) \
                 : "r"((a)[0]), "r"((a)[1]), "r"((a)[2]), "r"((a)[3]), \
                   "r"(b0), "r"(b1))

template <bool ASPLIT, int KDPAD>
__global__ void __launch_bounds__(256, 1)
hmma_gemm_kernel(const __half* __restrict__ Ahi, const __half* __restrict__ Alo,
                 size_t strideA,
                 const __half* __restrict__ Bhi, const __half* __restrict__ Blo,
                 const float* __restrict__ bias, const float* __restrict__ scale,
                 float* __restrict__ Cf, __half* __restrict__ Ch,
                 int Mrows, int Nfull, int leaky, int tpose) {
    extern __shared__ char smem[];
    constexpr int BSTR = KDPAD + 8;                 // halves
    constexpr int BPLANE = 128 * BSTR;              // halves
    constexpr int ASTAGE = (ASPLIT ? 2 : 1) * A_PLANE;
    __half* sBh = reinterpret_cast<__half*>(smem);
    __half* sBl = sBh + BPLANE;
    __half* sA0 = sBl + BPLANE;

    int tid = threadIdx.x;
    int lane = tid & 31, wid = tid >> 5;
    int wm = wid >> 1, wn = wid & 1;
    int k = blockIdx.z;
    int n0 = blockIdx.y * 128;
    int mg = blockIdx.x;

    const __half* Ah = Ahi + strideA * k;
    const __half* Al = ASPLIT ? (Alo + strideA * k) : nullptr;
    const __half* Bh = Bhi + ((size_t)k * Nfull + n0) * KDPAD;
    const __half* Bl = Blo + ((size_t)k * Nfull + n0) * KDPAD;

    // ---- load B resident (hi+lo, full K) ----
    constexpr int NCH = KDPAD >> 3;     // 16B chunks per row
    for (int i = tid; i < 128 * NCH; i += 256) {
        int r = i / NCH, c8 = (i % NCH) * 8;
        cp16(sBh + r * BSTR + c8, Bh + (size_t)r * KDPAD + c8, true);
        cp16(sBl + r * BSTR + c8, Bl + (size_t)r * KDPAD + c8, true);
    }
    CP_COMMIT();

    int rowL = tid >> 1;
    int kkL = (tid & 1) * 16;
    int soff = rowL * A_STRIDE + kkL;
    constexpr int NK = KDPAD >> 5;

    auto load_stage = [&](int s, int mt, int c) {
        int gm = (mg * MT_PER_BLK + mt) * 128 + rowL;
        bool aOk = gm < Mrows;
        const __half* pa = Ah + (size_t)gm * KDPAD + c * 32 + kkL;
        __half* dh = sA0 + s * ASTAGE + soff;
        cp16(dh,     pa,     aOk);
        cp16(dh + 8, pa + 8, aOk);
        if (ASPLIT) {
            const __half* pl = Al + (size_t)gm * KDPAD + c * 32 + kkL;
            cp16(dh + A_PLANE,     pl,     aOk);
            cp16(dh + A_PLANE + 8, pl + 8, aOk);
        }
        CP_COMMIT();
    };

    int aRow = wm * 32 + (lane & 15);
    int aCol = (lane >> 4) * 8;
    int bRow = wn * 64 + (lane >> 4) * 8 + (lane & 7);
    int bCol = ((lane >> 3) & 1) * 8;
    int g = lane >> 2, t = lane & 3;

    load_stage(0, 0, 0);
    int gpar = 0;

    for (int mt = 0; mt < MT_PER_BLK; mt++) {
        int mbase = (mg * MT_PER_BLK + mt) * 128;
        float acc[2][8][4];
#pragma unroll
        for (int mi = 0; mi < 2; mi++)
#pragma unroll
            for (int ni = 0; ni < 8; ni++)
#pragma unroll
                for (int i = 0; i < 4; i++) acc[mi][ni][i] = 0.f;

        for (int c = 0; c < NK; c++) {
            int s = gpar & 1;
            bool more = (c + 1 < NK) || (mt + 1 < MT_PER_BLK);
            if (c + 1 < NK)            load_stage(s ^ 1, mt, c + 1);
            else if (mt + 1 < MT_PER_BLK) load_stage(s ^ 1, mt + 1, 0);
            if (more) { CP_WAIT(1); } else { CP_WAIT(0); }
            __syncthreads();

            const __half* pAh = sA0 + s * ASTAGE;
            const __half* pAl = pAh + A_PLANE;

#pragma unroll
            for (int ks = 0; ks < 2; ks++) {
                uint32_t ah[2][4], al[2][4];
#pragma unroll
                for (int mi = 0; mi < 2; mi++) {
                    ldsm_x4(ah[mi], pAh + (aRow + mi * 16) * A_STRIDE + ks * 16 + aCol);
                    if (ASPLIT)
                        ldsm_x4(al[mi], pAl + (aRow + mi * 16) * A_STRIDE + ks * 16 + aCol);
                }
#pragma unroll
                for (int q = 0; q < 4; q++) {
                    uint32_t rh[4], rl[4];
                    const __half* bb = sBh + (size_t)(bRow + q * 16) * BSTR + c * 32 + ks * 16 + bCol;
                    ldsm_x4(rh, bb);
                    ldsm_x4(rl, bb + (sBl - sBh));
#pragma unroll
                    for (int p = 0; p < 2; p++) {
                        int ni = 2 * q + p;
#pragma unroll
                        for (int mi = 0; mi < 2; mi++) {
                            MMA16816(acc[mi][ni], ah[mi], rh[2 * p], rh[2 * p + 1]);
                            MMA16816(acc[mi][ni], ah[mi], rl[2 * p], rl[2 * p + 1]);
                            if (ASPLIT)
                                MMA16816(acc[mi][ni], al[mi], rh[2 * p], rh[2 * p + 1]);
                        }
                    }
                }
            }
            __syncthreads();
            gpar++;
        }

        // ---- epilogue for this m-tile (overlaps the prefetched next-tile load) ----
#pragma unroll
        for (int mi = 0; mi < 2; mi++) {
#pragma unroll
            for (int ni = 0; ni < 8; ni++) {
                int col = n0 + wn * 64 + ni * 8 + 2 * t;
                float b0 = 0.f, b1v = 0.f, s0 = 1.f, s1 = 1.f;
                if (bias) {
                    b0 = bias[(size_t)k * Nfull + col];
                    b1v = bias[(size_t)k * Nfull + col + 1];
                }
                if (scale) {
                    s0 = scale[(size_t)k * Nfull + col];
                    s1 = scale[(size_t)k * Nfull + col + 1];
                }
#pragma unroll
                for (int h = 0; h < 2; h++) {
                    int row = mbase + wm * 32 + mi * 16 + g + h * 8;
                    if (row >= Mrows) continue;
                    float v0 = acc[mi][ni][2 * h] + b0;
                    float v1 = acc[mi][ni][2 * h + 1] + b1v;
                    if (leaky) {
                        v0 = v0 > 0.f ? v0 : 0.01f * v0;
                        v1 = v1 > 0.f ? v1 : 0.01f * v1;
                    }
                    v0 *= s0; v1 *= s1;
                    if (Cf) {
                        size_t o = tpose
                            ? ((size_t)row * K_NETS + k) * Nfull + col
                            : ((size_t)k * Mrows + row) * Nfull + col;
                        *reinterpret_cast<float2*>(&Cf[o]) = make_float2(v0, v1);
                    } else {
                        size_t o = ((size_t)k * Mrows + row) * Nfull + col;
                        *reinterpret_cast<__half2*>(&Ch[o]) = __floats2half2_rn(v0, v1);
                    }
                }
            }
        }
    }
}

// ---------------- sum over net axis ----------------
__global__ void sum_nets_kernel(const float* __restrict__ phi, float* __restrict__ out, int M) {
    int m = blockIdx.x;
    int l = threadIdx.x;
    const float* base = phi + (size_t)m * K_NETS * L_DIM + l;
    float s = 0.f;
#pragma unroll 8
    for (int j = 0; j < K_NETS; j++) s += base[j * L_DIM];
    out[(size_t)m * L_DIM + l] = s;
}

// ---------------- psi(0) exact fp32 ----------------
__global__ void psi0_kernel(const float* __restrict__ b1eff, const float* __restrict__ W2,
                            const float* __restrict__ b2, const float* __restrict__ W3,
                            const float* __restrict__ scale, float* __restrict__ psi0) {
    int k = blockIdx.x;
    int t = threadIdx.x;
    __shared__ float h1[H_DIM], h2[H_DIM];
    float v = b1eff[k * H_DIM + t];
    h1[t] = v > 0.f ? v : 0.01f * v;
    __syncthreads();
    float a = b2[k * H_DIM + t];
    for (int d = 0; d < H_DIM; d++)
        a += h1[d] * W2[((size_t)k * H_DIM + d) * H_DIM + t];
    h2[t] = a > 0.f ? a : 0.01f * a;
    __syncthreads();
    if (t < L_DIM) {
        float s = 0.f;
        for (int d = 0; d < H_DIM; d++)
            s += h2[d] * W3[((size_t)k * H_DIM + d) * L_DIM + t];
        psi0[k * L_DIM + t] = s * scale[k * L_DIM + t];
    }
}

// ---------------- sequential Koopman scan: 2 blocks per batch ----------------
__global__ void __launch_bounds__(256)
scan_kernel(const float* __restrict__ phi,
            const float* __restrict__ psi,
            const float* __restrict__ psi0,
            const float* __restrict__ reL, const float* __restrict__ imL,
            float* __restrict__ predsum2) {
    int bid = blockIdx.x;
    int b = bid >> 1;
    int sel = bid & 1;
    int j0 = sel * 32;
    int tid = threadIdx.x;
    __shared__ float ps[32 * L_DIM];
    __shared__ float rsh[K_NETS], ish[K_NETS];
    if (tid < K_NETS) { rsh[tid] = reL[tid]; ish[tid] = imL[tid]; }

    float px[8], py[8], rj[8], ij[8], u0x[8], u0y[8];
    const float* phiB = phi + ((size_t)(b * T_DIM) * K_NETS + j0) * L_DIM;
    const float* psi0B = psi0 + (size_t)j0 * L_DIM;
#pragma unroll
    for (int q = 0; q < 8; q++) {
        int e = q * 256 + tid;
        float2 v = *reinterpret_cast<const float2*>(&phiB[e * 2]);
        px[q] = v.x; py[q] = v.y;
        float2 z = *reinterpret_cast<const float2*>(&psi0B[e * 2]);
        u0x[q] = z.x; u0y[q] = z.y;
    }
    __syncthreads();
#pragma unroll
    for (int q = 0; q < 8; q++) {
        int j = j0 + ((q * 256 + tid) >> 6);
        rj[q] = rsh[j]; ij[q] = ish[j];
    }

    for (int t = 0; t < TM1; t++) {
        const float* psiT = psi + ((size_t)(b * TM1 + t) * K_NETS + j0) * L_DIM;
#pragma unroll
        for (int q = 0; q < 8; q++) {
            int e = q * 256 + tid;
            float2 u = *reinterpret_cast<const float2*>(&psiT[e * 2]);
            float vx = px[q] + u.x - u0x[q];
            float vy = py[q] + u.y - u0y[q];
            px[q] = vx * rj[q] - vy * ij[q];
            py[q] = vx * ij[q] + vy * rj[q];
            ps[e * 2]     = px[q];
            ps[e * 2 + 1] = py[q];
        }
        __syncthreads();
        if (tid < L_DIM) {
            float s = 0.f;
#pragma unroll 8
            for (int j = 0; j < 32; j++) s += ps[j * L_DIM + tid];
            predsum2[(((size_t)sel * N_B + b) * TM1 + t) * L_DIM + tid] = s;
        }
        __syncthreads();
    }
}

// ---------------- decode ----------------
__global__ void decode_kernel(const float* __restrict__ phisum,
                              const float* __restrict__ predsum2,
                              const float* __restrict__ C_W,
                              float* __restrict__ out) {
    __shared__ float Cs[DX * L_DIM];
    __shared__ float rowY[L_DIM], rowP[L_DIM];
    int bt = blockIdx.x;
    int b = bt / TM1, t = bt % TM1;
    int tid = threadIdx.x;
    for (int i = tid; i < DX * L_DIM; i += 256) Cs[i] = C_W[i];
    if (tid < L_DIM)
        rowY[tid] = phisum[((size_t)(b * T_DIM + t + 1)) * L_DIM + tid];
    else {
        int l = tid - L_DIM;
        rowP[l] = predsum2[(size_t)bt * L_DIM + l]
                + predsum2[((size_t)N_B * TM1 + bt) * L_DIM + l];
    }
    __syncthreads();
    if (tid < 2 * DX) {
        int sel = tid >> 4, d = tid & 15;
        const float* row = sel ? rowP : rowY;
        float s = 0.f;
        for (int l = 0; l < L_DIM; l++) s += row[l] * Cs[d * L_DIM + l];
        out[(size_t)sel * N_B * TM1 * DX + (size_t)bt * DX + d] = s;
    }
}

// smem sizes
#define SMEM_L1  (2 * 128 * (KP1 + 8) * 2 + 2 * 2 * A_PLANE * 2)       // 61440
#define SMEM_L23 (2 * 128 * (H_DIM + 8) * 2 + 2 * 1 * A_PLANE * 2)     // 155648

// ---------------- launcher ----------------
extern "C" void kernel_launch(void* const* d_in, const int* in_sizes, int n_in,
                              void* d_out, int out_size) {
    const float* xs      = (const float*)d_in[0];
    const float* us      = (const float*)d_in[1];
    const float* x_gamma = (const float*)d_in[2];
    const float* x_beta  = (const float*)d_in[3];
    const float* xW1     = (const float*)d_in[4];
    const float* xb1     = (const float*)d_in[5];
    const float* xW2     = (const float*)d_in[6];
    const float* xb2     = (const float*)d_in[7];
    const float* xW3     = (const float*)d_in[8];
    const float* x_scale = (const float*)d_in[9];
    const float* u_gamma = (const float*)d_in[10];
    const float* u_beta  = (const float*)d_in[11];
    const float* uW1     = (const float*)d_in[12];
    const float* ub1     = (const float*)d_in[13];
    const float* uW2     = (const float*)d_in[14];
    const float* ub2     = (const float*)d_in[15];
    const float* uW3     = (const float*)d_in[16];
    const float* u_scale = (const float*)d_in[17];
    const float* reL     = (const float*)d_in[18];
    const float* imL     = (const float*)d_in[19];
    const float* C_W     = (const float*)d_in[20];
    float* out = (float*)d_out;

    float *b1ex, *b1eu, *phi, *psi, *psi0, *phisum, *predsum2;
    __half *xnhi, *xnlo, *unhi, *unlo, *w1xh, *w1xl, *w1uh, *w1ul;
    __half *h1, *h2;
    __half *w2xh, *w2xl, *w3xh, *w3xl, *w2uh, *w2ul, *w3uh, *w3ul;
    cudaGetSymbolAddress((void**)&xnhi, g_xnhi);
    cudaGetSymbolAddress((void**)&xnlo, g_xnlo);
    cudaGetSymbolAddress((void**)&unhi, g_unhi);
    cudaGetSymbolAddress((void**)&unlo, g_unlo);
    cudaGetSymbolAddress((void**)&b1ex, g_b1ex);
    cudaGetSymbolAddress((void**)&b1eu, g_b1eu);
    cudaGetSymbolAddress((void**)&w1xh, g_w1xh);
    cudaGetSymbolAddress((void**)&w1xl, g_w1xl);
    cudaGetSymbolAddress((void**)&w1uh, g_w1uh);
    cudaGetSymbolAddress((void**)&w1ul, g_w1ul);
    cudaGetSymbolAddress((void**)&h1, g_h1);
    cudaGetSymbolAddress((void**)&h2, g_h2);
    cudaGetSymbolAddress((void**)&w2xh, g_w2xt_hi);
    cudaGetSymbolAddress((void**)&w2xl, g_w2xt_lo);
    cudaGetSymbolAddress((void**)&w3xh, g_w3xt_hi);
    cudaGetSymbolAddress((void**)&w3xl, g_w3xt_lo);
    cudaGetSymbolAddress((void**)&w2uh, g_w2ut_hi);
    cudaGetSymbolAddress((void**)&w2ul, g_w2ut_lo);
    cudaGetSymbolAddress((void**)&w3uh, g_w3ut_hi);
    cudaGetSymbolAddress((void**)&w3ul, g_w3ut_lo);
    cudaGetSymbolAddress((void**)&phi, g_phi);
    cudaGetSymbolAddress((void**)&psi, g_psi);
    cudaGetSymbolAddress((void**)&psi0, g_psi0);
    cudaGetSymbolAddress((void**)&phisum, g_phisum);
    cudaGetSymbolAddress((void**)&predsum2, g_predsum2);

    cudaFuncSetAttribute((const void*)hmma_gemm_kernel<true, KP1>,
                         cudaFuncAttributeMaxDynamicSharedMemorySize, SMEM_L1);
    cudaFuncSetAttribute((const void*)hmma_gemm_kernel<false, H_DIM>,
                         cudaFuncAttributeMaxDynamicSharedMemorySize, SMEM_L23);

    dim3 tb(32, 8);
    bn_split_kernel<<<KP1, 256>>>(xs, xnhi, xnlo, MX, DX);                          // 0
    prep_w1_split_kernel<<<K_NETS, H_DIM>>>(x_gamma, x_beta, xW1, xb1,
                                            w1xh, w1xl, b1ex, DX);                  // 1
    transpose_split2_kernel<<<dim3(96, K_NETS), tb>>>(xW2, w2xh, w2xl,
                                                      xW3, w3xh, w3xl);             // 2
    hmma_gemm_kernel<true, KP1><<<dim3(4, 2, K_NETS), 256, SMEM_L1>>>(
        xnhi, xnlo, 0, w1xh, w1xl, b1ex, nullptr,
        nullptr, h1, MX, H_DIM, 1, 0);                                              // 3: L1x
    bn_split_kernel<<<KP1, 256>>>(us, unhi, unlo, MU, DU);                          // 4
    hmma_gemm_kernel<false, H_DIM><<<dim3(4, 2, K_NETS), 256, SMEM_L23>>>(
        h1, nullptr, (size_t)MX * H_DIM, w2xh, w2xl, xb2, nullptr,
        nullptr, h2, MX, H_DIM, 1, 0);                                              // 5: L2x
    hmma_gemm_kernel<false, H_DIM><<<dim3(4, 1, K_NETS), 256, SMEM_L23>>>(
        h2, nullptr, (size_t)MX * H_DIM, w3xh, w3xl, nullptr, x_scale,
        phi, nullptr, MX, L_DIM, 0, 1);                                             // 6: L3x
    sum_nets_kernel<<<MX, L_DIM>>>(phi, phisum, MX);                                // 7

    prep_w1_split_kernel<<<K_NETS, H_DIM>>>(u_gamma, u_beta, uW1, ub1,
                                            w1uh, w1ul, b1eu, DU);                  // 8
    transpose_split2_kernel<<<dim3(96, K_NETS), tb>>>(uW2, w2uh, w2ul,
                                                      uW3, w3uh, w3ul);             // 9
    hmma_gemm_kernel<true, KP1><<<dim3(4, 2, K_NETS), 256, SMEM_L1>>>(
        unhi, unlo, 0, w1uh, w1ul, b1eu, nullptr,
        nullptr, h1, MU, H_DIM, 1, 0);                                              // 10
    hmma_gemm_kernel<false, H_DIM><<<dim3(4, 2, K_NETS), 256, SMEM_L23>>>(
        h1, nullptr, (size_t)MU * H_DIM, w2uh, w2ul, ub2, nullptr,
        nullptr, h2, MU, H_DIM, 1, 0);                                              // 11
    hmma_gemm_kernel<false, H_DIM><<<dim3(4, 1, K_NETS), 256, SMEM_L23>>>(
        h2, nullptr, (size_t)MU * H_DIM, w3uh, w3ul, nullptr, u_scale,
        psi, nullptr, MU, L_DIM, 0, 1);                                             // 12

    psi0_kernel<<<K_NETS, H_DIM>>>(b1eu, uW2, ub2, uW3, u_scale, psi0);             // 13
    scan_kernel<<<2 * N_B, 256>>>(phi, psi, psi0, reL, imL, predsum2);              // 14
    decode_kernel<<<N_B * TM1, 256>>>(phisum, predsum2, C_W, out);                  // 15
}